// round 10
// baseline (speedup 1.0000x reference)
#include <cuda_runtime.h>

#define N_L    8192
#define N_H    32768
#define FDIM   128
#define KSEL   32

#define GRID   32
#define NBINS  (GRID * GRID * GRID)   // 32768
#define GLO    (-6.0f)
#define CS     0.375f                 // 12/32
#define CSINV  2.6666667f
#define MAXC   512                    // recorded cells per warp (fallback if exceeded)
#define FULLM  0xffffffffu

// ---------------- static device scratch (allocation-free) ----------------
__device__ float4 g_slp4[N_L];            // sorted sources (x,y,z,|l|^2)
__device__ float4 g_th4[N_H];             // sorted targets (x,y,z,|h|^2)
__device__ float4 g_xs4[N_L * (FDIM/4)];  // x rows permuted to sorted source order
__device__ int    g_thist[NBINS], g_tcur[NBINS], g_tstart[NBINS];
__device__ int    g_shist[NBINS], g_scur[NBINS], g_sstart[NBINS];
__device__ int    g_scell[NBINS];         // start | (count<<16)
__device__ int    g_tbin[N_H], g_sbin[N_L], g_spos[N_L], g_order[N_H];
__device__ int    g_tki[N_H * KSEL];      // selected sorted-source indices
__device__ float  g_tkw[N_H * KSEL];      // weights
__device__ float  g_twsum[N_H];

// ---------------- prep kernels ----------------
__global__ void zero_kernel() {
    int i = blockIdx.x * blockDim.x + threadIdx.x;
    if (i < NBINS) { g_thist[i] = 0; g_shist[i] = 0; }
}

__device__ __forceinline__ int cellc(float v) {
    int c = (int)((v - GLO) * CSINV);
    return min(max(c, 0), GRID - 1);
}

__device__ __forceinline__ int spread5(int b) {
    return (b & 1) | ((b & 2) << 2) | ((b & 4) << 4) | ((b & 8) << 6) | ((b & 16) << 8);
}

__global__ void bin_t_kernel(const float* __restrict__ pos_h) {
    int i = blockIdx.x * blockDim.x + threadIdx.x;
    if (i < N_H) {
        int cx = cellc(pos_h[3*i+0]);
        int cy = cellc(pos_h[3*i+1]);
        int cz = cellc(pos_h[3*i+2]);
        int m = spread5(cx) | (spread5(cy) << 1) | (spread5(cz) << 2);  // Morton
        g_tbin[i] = m;
        atomicAdd(&g_thist[m], 1);
    }
}

__global__ void bin_s_kernel(const float* __restrict__ pos_l) {
    int i = blockIdx.x * blockDim.x + threadIdx.x;
    if (i < N_L) {
        int cx = cellc(pos_l[3*i+0]);
        int cy = cellc(pos_l[3*i+1]);
        int cz = cellc(pos_l[3*i+2]);
        int b = (cz << 10) | (cy << 5) | cx;                            // linear
        g_sbin[i] = b;
        atomicAdd(&g_shist[b], 1);
    }
}

// Exclusive prefix over 32768 bins (1 block, 1024 threads, 32 bins/thread).
// sel=0: target arrays, sel=1: source arrays. Pointers resolved IN DEVICE CODE
// (passing __device__ symbols as host-side kernel args gives the host shadow
// address — that was the R9 bug).
__global__ void prefix32k_kernel(int sel) {
    const int* __restrict__ hist = sel ? g_shist : g_thist;
    int* cursor   = sel ? g_scur   : g_tcur;
    int* startarr = sel ? g_sstart : g_tstart;

    __shared__ int s_part[1024];
    int t = threadIdx.x;
    int base = t * 32;
    int sum = 0;
#pragma unroll 1
    for (int j = 0; j < 32; j++) sum += hist[base + j];
    s_part[t] = sum;
    __syncthreads();
    for (int d = 1; d < 1024; d <<= 1) {
        int add = (t >= d) ? s_part[t - d] : 0;
        __syncthreads();
        s_part[t] += add;
        __syncthreads();
    }
    int run = t ? s_part[t - 1] : 0;
#pragma unroll 1
    for (int j = 0; j < 32; j++) { cursor[base + j] = run; startarr[base + j] = run; run += hist[base + j]; }
}

__global__ void pack_scell_kernel() {
    int i = blockIdx.x * blockDim.x + threadIdx.x;
    if (i < NBINS) g_scell[i] = g_sstart[i] | (g_shist[i] << 16);
}

__global__ void scatter_t_kernel(const float* __restrict__ pos_h) {
    int i = blockIdx.x * blockDim.x + threadIdx.x;
    if (i < N_H) {
        float x = pos_h[3*i+0], y = pos_h[3*i+1], z = pos_h[3*i+2];
        int p = atomicAdd(&g_tcur[g_tbin[i]], 1);
        g_order[p] = i;
        g_th4[p] = make_float4(x, y, z, fmaf(x, x, fmaf(y, y, z * z)));
    }
}

__global__ void scatter_s_kernel(const float* __restrict__ pos_l) {
    int i = blockIdx.x * blockDim.x + threadIdx.x;
    if (i < N_L) {
        float x = pos_l[3*i+0], y = pos_l[3*i+1], z = pos_l[3*i+2];
        int p = atomicAdd(&g_scur[g_sbin[i]], 1);
        g_spos[i] = p;
        g_slp4[p] = make_float4(x, y, z, fmaf(x, x, fmaf(y, y, z * z)));
    }
}

__global__ void xcopy_kernel(const float* __restrict__ x) {
    // 256 threads = 8 rows per block, 32 float4 columns per row.
    int i = blockIdx.x * 8 + (threadIdx.x >> 5);   // source row
    int c = threadIdx.x & 31;                      // float4 column
    const float4* __restrict__ x4 = (const float4*)x;
    g_xs4[g_spos[i] * (FDIM/4) + c] = x4[i * (FDIM/4) + c];
}

// ---------------- select kernel ----------------
// s = l^2 - 2 h.l = d^2 - h^2 (ordering preserved per target)
__device__ __forceinline__ float cand_s(float hx, float hy, float hz, float4 p) {
    float dot = fmaf(hx, p.x, fmaf(hy, p.y, hz * p.z));
    return fmaf(-2.0f, dot, p.w);
}

__device__ __forceinline__ void insert32(float (&q)[KSEL], float s) {
    float cur = s;
#pragma unroll
    for (int j = 0; j < KSEL; j++) {
        float lo = fminf(q[j], cur);
        cur = fmaxf(q[j], cur);
        q[j] = lo;
    }
}

// Process one cell offset (dx,dy,dz) relative to warp base cell.
#define PROC_CELL(DX, DY, DZ)                                                     \
    do {                                                                          \
        int gx = bx + (DX), gy = by + (DY), gz = bz + (DZ);                       \
        if ((unsigned)gx < GRID && (unsigned)gy < GRID && (unsigned)gz < GRID) {  \
            int sc = g_scell[(gz << 10) | (gy << 5) | gx];                        \
            int pcnt = sc >> 16;                                                  \
            if (pcnt) {                                                           \
                float ccx = GLO + (gx + 0.5f) * CS;                               \
                float ccy = GLO + (gy + 0.5f) * CS;                               \
                float ccz = GLO + (gz + 0.5f) * CS;                               \
                float mx = fmaxf(fabsf(hx - ccx) - 0.5f * CS, 0.0f);              \
                float my = fmaxf(fabsf(hy - ccy) - 0.5f * CS, 0.0f);              \
                float mz = fmaxf(fabsf(hz - ccz) - 0.5f * CS, 0.0f);              \
                float md2 = fmaf(mx, mx, fmaf(my, my, mz * mz));                  \
                bool want = md2 <= q[KSEL - 1] + h2;                              \
                if (__any_sync(FULLM, want)) {                                    \
                    if (lane == 0) { if (ncell < MAXC) s_cells[w][ncell] = sc; ncell++; } \
                    int j0 = sc & 0xffff;                                         \
                    for (int j = j0; j < j0 + pcnt; ++j) {                        \
                        float4 pt = g_slp4[j];                                    \
                        float s = cand_s(hx, hy, hz, pt);                         \
                        if (s < q[KSEL - 1]) insert32(q, s);                      \
                    }                                                             \
                }                                                                 \
            }                                                                     \
        }                                                                         \
    } while (0)

__global__ __launch_bounds__(128) void select_kernel() {
    __shared__ int s_cells[4][MAXC];

    const int t    = threadIdx.x;
    const int lane = t & 31;
    const int w    = t >> 5;
    const int p    = (blockIdx.x * 4 + w) * 32 + lane;   // sorted target position

    const float4 th = g_th4[p];
    const float hx = th.x, hy = th.y, hz = th.z, h2 = th.w;

    // Warp base cell = lane 0's cell
    int cx = cellc(hx), cy = cellc(hy), cz = cellc(hz);
    const int bx = __shfl_sync(FULLM, cx, 0);
    const int by = __shfl_sync(FULLM, cy, 0);
    const int bz = __shfl_sync(FULLM, cz, 0);
    const float bcx = GLO + (bx + 0.5f) * CS;
    const float bcy = GLO + (by + 0.5f) * CS;
    const float bcz = GLO + (bz + 0.5f) * CS;
    const float e = fmaxf(fabsf(hx - bcx), fmaxf(fabsf(hy - bcy), fabsf(hz - bcz)));

    float q[KSEL];
#pragma unroll
    for (int j = 0; j < KSEL; j++) q[j] = __int_as_float(0x7f800000);

    int ncell = 0;   // lane-0 meaningful

    // ---- Pass 1: expanding-shell walk, value-only top-32 ----
    PROC_CELL(0, 0, 0);
    {
        float bnd0 = 0.5f * CS - e;
        bool done0 = (bnd0 > 0.0f) && (bnd0 * bnd0 > q[KSEL - 1] + h2);
        if (!__all_sync(FULLM, done0)) {
            for (int c = 1; c < GRID; ++c) {
                // z faces
                for (int f = 0; f < 2; ++f) {
                    int dz = f ? c : -c;
                    for (int dy = -c; dy <= c; ++dy)
                        for (int dx = -c; dx <= c; ++dx) PROC_CELL(dx, dy, dz);
                }
                // y faces (z interior)
                for (int f = 0; f < 2; ++f) {
                    int dy = f ? c : -c;
                    for (int dz = -c + 1; dz <= c - 1; ++dz)
                        for (int dx = -c; dx <= c; ++dx) PROC_CELL(dx, dy, dz);
                }
                // x faces (y,z interior)
                for (int f = 0; f < 2; ++f) {
                    int dx = f ? c : -c;
                    for (int dz = -c + 1; dz <= c - 1; ++dz)
                        for (int dy = -c + 1; dy <= c - 1; ++dy) PROC_CELL(dx, dy, dz);
                }
                float bnd = (c + 0.5f) * CS - e;
                bool done = (bnd > 0.0f) && (bnd * bnd > q[KSEL - 1] + h2);
                if (__all_sync(FULLM, done)) break;
            }
        }
    }
    __syncwarp();

    // ---- Pass 2: rescan recorded cells (bit-identical fmaf), recover idx+w ----
    const float T = q[KSEL - 1];
    const int nc_raw = __shfl_sync(FULLM, ncell, 0);
    const bool ovf = nc_raw > MAXC;
    const int nc = ovf ? 0 : nc_raw;

    int cnt = 0;
    float wsum = 0.0f;
    const int ob = p * KSEL;

    if (!ovf) {
#pragma unroll 1
        for (int ci = 0; ci < nc; ++ci) {
            int sc = s_cells[w][ci];
            int j0 = sc & 0xffff, n = sc >> 16;
            for (int j = j0; j < j0 + n; ++j) {
                float4 pt = g_slp4[j];
                float s = cand_s(hx, hy, hz, pt);
                if (s <= T && cnt < KSEL) {
                    float wg = 1.0f / fmaxf(s + h2, 1e-16f);
                    g_tki[ob + cnt] = j;
                    g_tkw[ob + cnt] = wg;
                    wsum += wg;
                    cnt++;
                }
            }
        }
    } else {
        // Extremely rare fallback: brute rescan of all sorted sources (still exact).
#pragma unroll 1
        for (int j = 0; j < N_L; ++j) {
            float4 pt = g_slp4[j];
            float s = cand_s(hx, hy, hz, pt);
            if (s <= T && cnt < KSEL) {
                float wg = 1.0f / fmaxf(s + h2, 1e-16f);
                g_tki[ob + cnt] = j;
                g_tkw[ob + cnt] = wg;
                wsum += wg;
                cnt++;
            }
        }
    }
    // Safety pad: keep gather's 32-wide shuffle consistent with wsum no matter what.
    while (cnt < KSEL) { g_tki[ob + cnt] = 0; g_tkw[ob + cnt] = 0.0f; cnt++; }
    g_twsum[p] = wsum;
}

// ---------------- gather kernel: one warp per target ----------------
__global__ __launch_bounds__(256) void gather_kernel(float* __restrict__ out) {
    const int lane = threadIdx.x & 31;
    const int p = blockIdx.x * 8 + (threadIdx.x >> 5);   // sorted target position

    int   myid = g_tki[p * KSEL + lane];
    float myw  = g_tkw[p * KSEL + lane];

    float4 acc = make_float4(0.f, 0.f, 0.f, 0.f);
#pragma unroll
    for (int k = 0; k < KSEL; k++) {
        int   id = __shfl_sync(FULLM, myid, k);
        float wk = __shfl_sync(FULLM, myw, k);
        float4 v = g_xs4[id * (FDIM/4) + lane];
        acc.x = fmaf(wk, v.x, acc.x);
        acc.y = fmaf(wk, v.y, acc.y);
        acc.z = fmaf(wk, v.z, acc.z);
        acc.w = fmaf(wk, v.w, acc.w);
    }
    float inv = 1.0f / g_twsum[p];
    int o = g_order[p];
    float4* out4 = (float4*)out;
    out4[o * (FDIM/4) + lane] =
        make_float4(acc.x * inv, acc.y * inv, acc.z * inv, acc.w * inv);
}

extern "C" void kernel_launch(void* const* d_in, const int* in_sizes, int n_in,
                              void* d_out, int out_size) {
    const float* x     = (const float*)d_in[0];
    const float* pos_l = (const float*)d_in[1];
    const float* pos_h = (const float*)d_in[2];
    float* out = (float*)d_out;

    zero_kernel<<<NBINS / 256, 256>>>();
    bin_t_kernel<<<N_H / 256, 256>>>(pos_h);
    bin_s_kernel<<<N_L / 256, 256>>>(pos_l);
    prefix32k_kernel<<<1, 1024>>>(0);   // targets
    prefix32k_kernel<<<1, 1024>>>(1);   // sources
    pack_scell_kernel<<<NBINS / 256, 256>>>();
    scatter_t_kernel<<<N_H / 256, 256>>>(pos_h);
    scatter_s_kernel<<<N_L / 256, 256>>>(pos_l);
    xcopy_kernel<<<N_L / 8, 256>>>(x);
    select_kernel<<<N_H / 128, 128>>>();
    gather_kernel<<<N_H / 8, 256>>>(out);
}

// round 11
// speedup vs baseline: 6.6664x; 6.6664x over previous
#include <cuda_runtime.h>

#define N_L    8192
#define N_H    32768
#define FDIM   128
#define KSEL   32

#define GRID   32
#define NBINS  (GRID * GRID * GRID)   // 32768
#define GLO    (-6.0f)
#define CS     0.375f                 // 12/32
#define HALF   (0.5f * CS)
#define CSINV  2.6666667f
#define FULLM  0xffffffffu

// ---------------- static device scratch (allocation-free) ----------------
__device__ float4 g_slp4[N_L];            // sorted sources (x,y,z,|l|^2)
__device__ float4 g_th4[N_H];             // sorted targets (x,y,z,|h|^2)
__device__ float4 g_xs4[N_L * (FDIM/4)];  // x rows permuted to sorted source order
__device__ int    g_thist[NBINS], g_tcur[NBINS], g_tstart[NBINS];
__device__ int    g_shist[NBINS], g_scur[NBINS], g_sstart[NBINS];
__device__ int    g_scell[NBINS];         // start | (count<<16)
__device__ int    g_tbin[N_H], g_sbin[N_L], g_spos[N_L], g_order[N_H];
__device__ int    g_tki[N_H * KSEL];
__device__ float  g_tkw[N_H * KSEL];
__device__ float  g_twsum[N_H];

// ---------------- prep kernels ----------------
__global__ void zero_kernel() {
    int i = blockIdx.x * blockDim.x + threadIdx.x;
    if (i < NBINS) { g_thist[i] = 0; g_shist[i] = 0; }
}

__device__ __forceinline__ int cellc(float v) {
    int c = (int)((v - GLO) * CSINV);
    return min(max(c, 0), GRID - 1);
}

__device__ __forceinline__ int spread5(int b) {
    return (b & 1) | ((b & 2) << 2) | ((b & 4) << 4) | ((b & 8) << 6) | ((b & 16) << 8);
}

__global__ void bin_t_kernel(const float* __restrict__ pos_h) {
    int i = blockIdx.x * blockDim.x + threadIdx.x;
    if (i < N_H) {
        int cx = cellc(pos_h[3*i+0]);
        int cy = cellc(pos_h[3*i+1]);
        int cz = cellc(pos_h[3*i+2]);
        int m = spread5(cx) | (spread5(cy) << 1) | (spread5(cz) << 2);  // Morton
        g_tbin[i] = m;
        atomicAdd(&g_thist[m], 1);
    }
}

__global__ void bin_s_kernel(const float* __restrict__ pos_l) {
    int i = blockIdx.x * blockDim.x + threadIdx.x;
    if (i < N_L) {
        int cx = cellc(pos_l[3*i+0]);
        int cy = cellc(pos_l[3*i+1]);
        int cz = cellc(pos_l[3*i+2]);
        int b = (cz << 10) | (cy << 5) | cx;                            // linear
        g_sbin[i] = b;
        atomicAdd(&g_shist[b], 1);
    }
}

// Exclusive prefix over 32768 bins. int4-vectorized loads/stores (the R10
// version's scalar strided accesses made this 85us). sel=0: targets, 1: sources.
// Pointers resolved in device code (host-side __device__ symbol args = R9 bug).
__global__ void prefix32k_kernel(int sel) {
    const int* __restrict__ hist = sel ? g_shist : g_thist;
    int* cursor   = sel ? g_scur   : g_tcur;
    int* startarr = sel ? g_sstart : g_tstart;

    __shared__ int s_part[1024];
    int t = threadIdx.x;
    int base = t * 32;
    const int4* h4 = (const int4*)(hist + base);
    int4 v[8];
    int sum = 0;
#pragma unroll
    for (int j = 0; j < 8; j++) {
        v[j] = h4[j];
        sum += v[j].x + v[j].y + v[j].z + v[j].w;
    }
    s_part[t] = sum;
    __syncthreads();
    for (int d = 1; d < 1024; d <<= 1) {
        int add = (t >= d) ? s_part[t - d] : 0;
        __syncthreads();
        s_part[t] += add;
        __syncthreads();
    }
    int run = t ? s_part[t - 1] : 0;
#pragma unroll
    for (int j = 0; j < 8; j++) {
        int4 c;
        c.x = run; run += v[j].x;
        c.y = run; run += v[j].y;
        c.z = run; run += v[j].z;
        c.w = run; run += v[j].w;
        ((int4*)(cursor   + base))[j] = c;
        ((int4*)(startarr + base))[j] = c;
    }
}

__global__ void pack_scell_kernel() {
    int i = blockIdx.x * blockDim.x + threadIdx.x;
    if (i < NBINS) g_scell[i] = g_sstart[i] | (g_shist[i] << 16);
}

__global__ void scatter_t_kernel(const float* __restrict__ pos_h) {
    int i = blockIdx.x * blockDim.x + threadIdx.x;
    if (i < N_H) {
        float x = pos_h[3*i+0], y = pos_h[3*i+1], z = pos_h[3*i+2];
        int p = atomicAdd(&g_tcur[g_tbin[i]], 1);
        g_order[p] = i;
        g_th4[p] = make_float4(x, y, z, fmaf(x, x, fmaf(y, y, z * z)));
    }
}

__global__ void scatter_s_kernel(const float* __restrict__ pos_l) {
    int i = blockIdx.x * blockDim.x + threadIdx.x;
    if (i < N_L) {
        float x = pos_l[3*i+0], y = pos_l[3*i+1], z = pos_l[3*i+2];
        int p = atomicAdd(&g_scur[g_sbin[i]], 1);
        g_spos[i] = p;
        g_slp4[p] = make_float4(x, y, z, fmaf(x, x, fmaf(y, y, z * z)));
    }
}

__global__ void xcopy_kernel(const float* __restrict__ x) {
    int i = blockIdx.x * 8 + (threadIdx.x >> 5);   // source row
    int c = threadIdx.x & 31;                      // float4 column
    const float4* __restrict__ x4 = (const float4*)x;
    g_xs4[g_spos[i] * (FDIM/4) + c] = x4[i * (FDIM/4) + c];
}

// ---------------- select kernel ----------------
__device__ __forceinline__ float cand_s(float hx, float hy, float hz, float4 p) {
    float dot = fmaf(hx, p.x, fmaf(hy, p.y, hz * p.z));
    return fmaf(-2.0f, dot, p.w);
}

__device__ __forceinline__ void insert32(float (&q)[KSEL], float s) {
    float cur = s;
#pragma unroll
    for (int j = 0; j < KSEL; j++) {
        float lo = fminf(q[j], cur);
        cur = fmaxf(q[j], cur);
        q[j] = lo;
    }
}

// Per-lane cell visit, pass 1 (evolving threshold thr = q[31]+h2).
#define PROC1(DX, DY, DZ)                                                          \
    do {                                                                           \
        int gx = cx + (DX), gy = cy + (DY), gz = cz + (DZ);                        \
        bool inb = ((unsigned)gx < GRID) & ((unsigned)gy < GRID) & ((unsigned)gz < GRID); \
        int sc = inb ? g_scell[(gz << 10) | (gy << 5) | gx] : 0;                   \
        int pcnt = sc >> 16;                                                       \
        bool act = (!mydone) & (pcnt > 0);                                         \
        if (act) {                                                                 \
            float mx = fmaxf(fabsf(hx - (GLO + (gx + 0.5f) * CS)) - HALF, 0.0f);   \
            float my = fmaxf(fabsf(hy - (GLO + (gy + 0.5f) * CS)) - HALF, 0.0f);   \
            float mz = fmaxf(fabsf(hz - (GLO + (gz + 0.5f) * CS)) - HALF, 0.0f);   \
            act = fmaf(mx, mx, fmaf(my, my, mz * mz)) <= q[KSEL - 1] + h2;         \
        }                                                                          \
        int n = act ? pcnt : 0;                                                    \
        int nmax = __reduce_max_sync(FULLM, n);                                    \
        int j0 = sc & 0xffff;                                                      \
        for (int j = 0; j < nmax; ++j) {                                           \
            float4 pt = g_slp4[(j < n) ? j0 + j : 0];                              \
            float s = cand_s(hx, hy, hz, pt);                                      \
            if (j < n && s < q[KSEL - 1]) insert32(q, s);                          \
        }                                                                          \
    } while (0)

// Per-lane cell visit, pass 2 (fixed threshold T; collect idx+weight).
#define PROC2(DX, DY, DZ)                                                          \
    do {                                                                           \
        int gx = cx + (DX), gy = cy + (DY), gz = cz + (DZ);                        \
        bool inb = ((unsigned)gx < GRID) & ((unsigned)gy < GRID) & ((unsigned)gz < GRID); \
        int sc = inb ? g_scell[(gz << 10) | (gy << 5) | gx] : 0;                   \
        int pcnt = sc >> 16;                                                       \
        bool act = (!mydone) & (pcnt > 0);                                         \
        if (act) {                                                                 \
            float mx = fmaxf(fabsf(hx - (GLO + (gx + 0.5f) * CS)) - HALF, 0.0f);   \
            float my = fmaxf(fabsf(hy - (GLO + (gy + 0.5f) * CS)) - HALF, 0.0f);   \
            float mz = fmaxf(fabsf(hz - (GLO + (gz + 0.5f) * CS)) - HALF, 0.0f);   \
            act = fmaf(mx, mx, fmaf(my, my, mz * mz)) <= T + h2;                   \
        }                                                                          \
        int n = act ? pcnt : 0;                                                    \
        int nmax = __reduce_max_sync(FULLM, n);                                    \
        int j0 = sc & 0xffff;                                                      \
        for (int j = 0; j < nmax; ++j) {                                           \
            float4 pt = g_slp4[(j < n) ? j0 + j : 0];                              \
            float s = cand_s(hx, hy, hz, pt);                                      \
            if (j < n && s <= T && cnt < KSEL) {                                   \
                float wg = 1.0f / fmaxf(s + h2, 1e-16f);                           \
                g_tki[ob + cnt] = j0 + j;                                          \
                g_tkw[ob + cnt] = wg;                                              \
                wsum += wg;                                                        \
                cnt++;                                                             \
            }                                                                      \
        }                                                                          \
    } while (0)

// Enumerate Chebyshev shell c (>=1) offsets around the per-lane base cell.
#define SHELL(PROC_)                                                               \
    do {                                                                           \
        for (int f = 0; f < 2; ++f) {                                              \
            int dz = f ? c : -c;                                                   \
            for (int dy = -c; dy <= c; ++dy)                                       \
                for (int dx = -c; dx <= c; ++dx) PROC_(dx, dy, dz);                \
        }                                                                          \
        for (int f = 0; f < 2; ++f) {                                              \
            int dy = f ? c : -c;                                                   \
            for (int dz = -c + 1; dz <= c - 1; ++dz)                               \
                for (int dx = -c; dx <= c; ++dx) PROC_(dx, dy, dz);                \
        }                                                                          \
        for (int f = 0; f < 2; ++f) {                                              \
            int dx = f ? c : -c;                                                   \
            for (int dz = -c + 1; dz <= c - 1; ++dz)                               \
                for (int dy = -c + 1; dy <= c - 1; ++dy) PROC_(dx, dy, dz);        \
        }                                                                          \
    } while (0)

__global__ __launch_bounds__(128) void select_kernel() {
    const int p = blockIdx.x * blockDim.x + threadIdx.x;   // one thread = one target

    const float4 th = g_th4[p];
    const float hx = th.x, hy = th.y, hz = th.z, h2 = th.w;

    // Per-lane base cell: e <= CS/2 by construction (no warp-spread blowup).
    const int cx = cellc(hx), cy = cellc(hy), cz = cellc(hz);
    const float e = fmaxf(fabsf(hx - (GLO + (cx + 0.5f) * CS)),
                    fmaxf(fabsf(hy - (GLO + (cy + 0.5f) * CS)),
                          fabsf(hz - (GLO + (cz + 0.5f) * CS))));

    float q[KSEL];
#pragma unroll
    for (int j = 0; j < KSEL; j++) q[j] = __int_as_float(0x7f800000);

    // ---- Pass 1: per-lane expanding shells, value-only top-32 ----
    {
        bool mydone = false;
        PROC1(0, 0, 0);
        {
            float bnd = 0.5f * CS - e;
            mydone = (bnd > 0.0f) && (bnd * bnd > q[KSEL - 1] + h2);
        }
        if (!__all_sync(FULLM, mydone)) {
            for (int c = 1; c < GRID; ++c) {
                SHELL(PROC1);
                float bnd = (c + 0.5f) * CS - e;
                bool d2 = (bnd > 0.0f) && (bnd * bnd > q[KSEL - 1] + h2);
                mydone = mydone || d2;
                if (__all_sync(FULLM, mydone)) break;
            }
        }
    }

    // ---- Pass 2: repeat walk with fixed T; bit-identical fmaf; collect ----
    const float T = q[KSEL - 1];
    int cnt = 0;
    float wsum = 0.0f;
    const int ob = p * KSEL;
    {
        bool mydone = false;
        PROC2(0, 0, 0);
        {
            float bnd = 0.5f * CS - e;
            mydone = (bnd > 0.0f) && (bnd * bnd > T + h2);
        }
        if (!__all_sync(FULLM, mydone)) {
            for (int c = 1; c < GRID; ++c) {
                SHELL(PROC2);
                float bnd = (c + 0.5f) * CS - e;
                bool d2 = (bnd > 0.0f) && (bnd * bnd > T + h2);
                mydone = mydone || d2;
                if (__all_sync(FULLM, mydone)) break;
            }
        }
    }
    // Safety pad: keep gather's 32-wide shuffle consistent with wsum.
    while (cnt < KSEL) { g_tki[ob + cnt] = 0; g_tkw[ob + cnt] = 0.0f; cnt++; }
    g_twsum[p] = wsum;
}

// ---------------- gather kernel: one warp per target ----------------
__global__ __launch_bounds__(256) void gather_kernel(float* __restrict__ out) {
    const int lane = threadIdx.x & 31;
    const int p = blockIdx.x * 8 + (threadIdx.x >> 5);

    int   myid = g_tki[p * KSEL + lane];
    float myw  = g_tkw[p * KSEL + lane];

    float4 acc = make_float4(0.f, 0.f, 0.f, 0.f);
#pragma unroll
    for (int k = 0; k < KSEL; k++) {
        int   id = __shfl_sync(FULLM, myid, k);
        float wk = __shfl_sync(FULLM, myw, k);
        float4 v = g_xs4[id * (FDIM/4) + lane];
        acc.x = fmaf(wk, v.x, acc.x);
        acc.y = fmaf(wk, v.y, acc.y);
        acc.z = fmaf(wk, v.z, acc.z);
        acc.w = fmaf(wk, v.w, acc.w);
    }
    float inv = 1.0f / g_twsum[p];
    int o = g_order[p];
    float4* out4 = (float4*)out;
    out4[o * (FDIM/4) + lane] =
        make_float4(acc.x * inv, acc.y * inv, acc.z * inv, acc.w * inv);
}

extern "C" void kernel_launch(void* const* d_in, const int* in_sizes, int n_in,
                              void* d_out, int out_size) {
    const float* x     = (const float*)d_in[0];
    const float* pos_l = (const float*)d_in[1];
    const float* pos_h = (const float*)d_in[2];
    float* out = (float*)d_out;

    zero_kernel<<<NBINS / 256, 256>>>();
    bin_t_kernel<<<N_H / 256, 256>>>(pos_h);
    bin_s_kernel<<<N_L / 256, 256>>>(pos_l);
    prefix32k_kernel<<<1, 1024>>>(0);
    prefix32k_kernel<<<1, 1024>>>(1);
    pack_scell_kernel<<<NBINS / 256, 256>>>();
    scatter_t_kernel<<<N_H / 256, 256>>>(pos_h);
    scatter_s_kernel<<<N_L / 256, 256>>>(pos_l);
    xcopy_kernel<<<N_L / 8, 256>>>(x);
    select_kernel<<<N_H / 128, 128>>>();
    gather_kernel<<<N_H / 8, 256>>>(out);
}

// round 12
// speedup vs baseline: 20.7502x; 3.1126x over previous
#include <cuda_runtime.h>

#define N_L    8192
#define N_H    32768
#define FDIM   128
#define KSEL   32

#define GRID   32
#define NBINS  (GRID * GRID * GRID)
#define GLO    (-6.0f)
#define CS     0.375f
#define HALF   (0.5f * CS)
#define CSINV  2.6666667f
#define FULLM  0xffffffffu

// ---------------- static device scratch (allocation-free) ----------------
__device__ float4 g_slp4[N_L];            // sorted sources (x,y,z,|l|^2)
__device__ float4 g_th4[N_H];             // sorted targets (x,y,z,|h|^2)
__device__ float4 g_xs4[N_L * (FDIM/4)];  // x rows permuted to sorted source order
__device__ int    g_thist[NBINS], g_tcur[NBINS], g_tstart[NBINS];
__device__ int    g_shist[NBINS], g_scur[NBINS], g_sstart[NBINS];
__device__ int    g_scell[NBINS];         // start | (count<<16)
__device__ int    g_tbin[N_H], g_sbin[N_L], g_spos[N_L], g_order[N_H];
__device__ int    g_tki[N_H * KSEL];
__device__ float  g_tkw[N_H * KSEL];
__device__ float  g_twsum[N_H];

// ---------------- prep kernels ----------------
__global__ void zero_kernel() {
    int i = blockIdx.x * blockDim.x + threadIdx.x;
    if (i < NBINS) { g_thist[i] = 0; g_shist[i] = 0; }
}

__device__ __forceinline__ int cellc(float v) {
    int c = (int)((v - GLO) * CSINV);
    return min(max(c, 0), GRID - 1);
}
// coordinate -> clamped cell via floor (safe for v < GLO)
__device__ __forceinline__ int cellof(float v) {
    int c = (int)floorf((v - GLO) * CSINV);
    return min(max(c, 0), GRID - 1);
}

__device__ __forceinline__ int spread5(int b) {
    return (b & 1) | ((b & 2) << 2) | ((b & 4) << 4) | ((b & 8) << 6) | ((b & 16) << 8);
}

__global__ void bin_t_kernel(const float* __restrict__ pos_h) {
    int i = blockIdx.x * blockDim.x + threadIdx.x;
    if (i < N_H) {
        int cx = cellc(pos_h[3*i+0]);
        int cy = cellc(pos_h[3*i+1]);
        int cz = cellc(pos_h[3*i+2]);
        int m = spread5(cx) | (spread5(cy) << 1) | (spread5(cz) << 2);  // Morton
        g_tbin[i] = m;
        atomicAdd(&g_thist[m], 1);
    }
}

__global__ void bin_s_kernel(const float* __restrict__ pos_l) {
    int i = blockIdx.x * blockDim.x + threadIdx.x;
    if (i < N_L) {
        int cx = cellc(pos_l[3*i+0]);
        int cy = cellc(pos_l[3*i+1]);
        int cz = cellc(pos_l[3*i+2]);
        int b = (cz << 10) | (cy << 5) | cx;                            // linear
        g_sbin[i] = b;
        atomicAdd(&g_shist[b], 1);
    }
}

// Exclusive prefix over 32768 bins, int4-vectorized. sel resolved in device code.
__global__ void prefix32k_kernel(int sel) {
    const int* __restrict__ hist = sel ? g_shist : g_thist;
    int* cursor   = sel ? g_scur   : g_tcur;
    int* startarr = sel ? g_sstart : g_tstart;

    __shared__ int s_part[1024];
    int t = threadIdx.x;
    int base = t * 32;
    const int4* h4 = (const int4*)(hist + base);
    int4 v[8];
    int sum = 0;
#pragma unroll
    for (int j = 0; j < 8; j++) {
        v[j] = h4[j];
        sum += v[j].x + v[j].y + v[j].z + v[j].w;
    }
    s_part[t] = sum;
    __syncthreads();
    for (int d = 1; d < 1024; d <<= 1) {
        int add = (t >= d) ? s_part[t - d] : 0;
        __syncthreads();
        s_part[t] += add;
        __syncthreads();
    }
    int run = t ? s_part[t - 1] : 0;
#pragma unroll
    for (int j = 0; j < 8; j++) {
        int4 c;
        c.x = run; run += v[j].x;
        c.y = run; run += v[j].y;
        c.z = run; run += v[j].z;
        c.w = run; run += v[j].w;
        ((int4*)(cursor   + base))[j] = c;
        ((int4*)(startarr + base))[j] = c;
    }
}

__global__ void pack_scell_kernel() {
    int i = blockIdx.x * blockDim.x + threadIdx.x;
    if (i < NBINS) g_scell[i] = g_sstart[i] | (g_shist[i] << 16);
}

__global__ void scatter_t_kernel(const float* __restrict__ pos_h) {
    int i = blockIdx.x * blockDim.x + threadIdx.x;
    if (i < N_H) {
        float x = pos_h[3*i+0], y = pos_h[3*i+1], z = pos_h[3*i+2];
        int p = atomicAdd(&g_tcur[g_tbin[i]], 1);
        g_order[p] = i;
        g_th4[p] = make_float4(x, y, z, fmaf(x, x, fmaf(y, y, z * z)));
    }
}

__global__ void scatter_s_kernel(const float* __restrict__ pos_l) {
    int i = blockIdx.x * blockDim.x + threadIdx.x;
    if (i < N_L) {
        float x = pos_l[3*i+0], y = pos_l[3*i+1], z = pos_l[3*i+2];
        int p = atomicAdd(&g_scur[g_sbin[i]], 1);
        g_spos[i] = p;
        g_slp4[p] = make_float4(x, y, z, fmaf(x, x, fmaf(y, y, z * z)));
    }
}

__global__ void xcopy_kernel(const float* __restrict__ x) {
    int i = blockIdx.x * 8 + (threadIdx.x >> 5);
    int c = threadIdx.x & 31;
    const float4* __restrict__ x4 = (const float4*)x;
    g_xs4[g_spos[i] * (FDIM/4) + c] = x4[i * (FDIM/4) + c];
}

// ---------------- select kernel ----------------
__device__ __forceinline__ float cand_s(float hx, float hy, float hz, float4 p) {
    float dot = fmaf(hx, p.x, fmaf(hy, p.y, hz * p.z));
    return fmaf(-2.0f, dot, p.w);
}

__device__ __forceinline__ void insert32(float (&q)[KSEL], float s) {
    float cur = s;
#pragma unroll
    for (int j = 0; j < KSEL; j++) {
        float lo = fminf(q[j], cur);
        cur = fmaxf(q[j], cur);
        q[j] = lo;
    }
}

__device__ __forceinline__ float mindc(float h, int g) {
    return fmaxf(fabsf(h - (GLO + (g + 0.5f) * CS)) - HALF, 0.0f);
}

__global__ __launch_bounds__(128) void select_kernel() {
    const int p = blockIdx.x * blockDim.x + threadIdx.x;   // one thread = one target

    const float4 th = g_th4[p];
    const float hx = th.x, hy = th.y, hz = th.z, h2 = th.w;

    const int cx = cellc(hx), cy = cellc(hy), cz = cellc(hz);
    const float e = fmaxf(fabsf(hx - (GLO + (cx + 0.5f) * CS)),
                    fmaxf(fabsf(hy - (GLO + (cy + 0.5f) * CS)),
                          fabsf(hz - (GLO + (cz + 0.5f) * CS))));

    // ---- Count-prepass: smallest cube (Chebyshev radius c) holding >= 32 sources ----
    int cc = 0;
    for (; cc < GRID; ++cc) {
        int zlo = max(cz - cc, 0), zhi = min(cz + cc, GRID - 1);
        int ylo = max(cy - cc, 0), yhi = min(cy + cc, GRID - 1);
        int xlo = max(cx - cc, 0), xhi = min(cx + cc, GRID - 1);
        int total = 0;
        for (int gz = zlo; gz <= zhi; ++gz)
            for (int gy = ylo; gy <= yhi; ++gy) {
                int rowb = (gz << 10) | (gy << 5);
                int sc0 = g_scell[rowb | xlo];
                int sc1 = g_scell[rowb | xhi];
                total += (sc1 & 0xffff) + (sc1 >> 16) - (sc0 & 0xffff);
            }
        if (total >= KSEL) break;
    }
    const float reach = (cc + 0.5f) * CS + e;
    const float thr0 = 3.0f * reach * reach;   // d32^2 <= cube corner distance^2

    float q[KSEL];
#pragma unroll
    for (int j = 0; j < KSEL; j++) q[j] = __int_as_float(0x7f800000);

    // ---- Pass 1: rows near-to-far, analytic x-span, streamed scan ----
    {
        int zdone = 0;   // bit0: -z exhausted, bit1: +z exhausted
        for (int iz = 0; iz < 2 * GRID && zdone != 3; ++iz) {
            int dz = (iz & 1) ? ((iz >> 1) + 1) : -(iz >> 1);
            if (iz && ((dz < 0 && (zdone & 1)) || (dz > 0 && (zdone & 2)))) continue;
            int gz = cz + dz;
            if ((unsigned)gz >= GRID) { zdone |= (dz < 0) ? 1 : 2; continue; }
            float mz = mindc(hz, gz);
            float mz2 = mz * mz;
            float thr = fminf(thr0, q[KSEL - 1] + h2);
            if (mz2 > thr) { if (dz) zdone |= (dz < 0) ? 1 : 2; continue; }

            int ydone = 0;
            for (int iy = 0; iy < 2 * GRID && ydone != 3; ++iy) {
                int dy = (iy & 1) ? ((iy >> 1) + 1) : -(iy >> 1);
                if (iy && ((dy < 0 && (ydone & 1)) || (dy > 0 && (ydone & 2)))) continue;
                int gy = cy + dy;
                if ((unsigned)gy >= GRID) { ydone |= (dy < 0) ? 1 : 2; continue; }
                float my = mindc(hy, gy);
                thr = fminf(thr0, q[KSEL - 1] + h2);
                float rem = thr - mz2 - my * my;
                if (rem < 0.0f) { if (dy) ydone |= (dy < 0) ? 1 : 2; continue; }

                float halfw = sqrtf(rem);
                int gx0 = cellof(hx - halfw);
                int gx1 = cellof(hx + halfw);
                int rowb = (gz << 10) | (gy << 5);
                int sc0 = g_scell[rowb | gx0];
                int sc1 = g_scell[rowb | gx1];
                int j = sc0 & 0xffff;
                int j1 = (sc1 & 0xffff) + (sc1 >> 16);

                for (; j + 4 <= j1; j += 4) {
                    float4 p0 = g_slp4[j + 0];
                    float4 p1 = g_slp4[j + 1];
                    float4 p2 = g_slp4[j + 2];
                    float4 p3 = g_slp4[j + 3];
                    float s0 = cand_s(hx, hy, hz, p0);
                    float s1 = cand_s(hx, hy, hz, p1);
                    float s2 = cand_s(hx, hy, hz, p2);
                    float s3 = cand_s(hx, hy, hz, p3);
                    float m = fminf(fminf(s0, s1), fminf(s2, s3));
                    if (m < q[KSEL - 1]) {
                        if (s0 < q[KSEL - 1]) insert32(q, s0);
                        if (s1 < q[KSEL - 1]) insert32(q, s1);
                        if (s2 < q[KSEL - 1]) insert32(q, s2);
                        if (s3 < q[KSEL - 1]) insert32(q, s3);
                    }
                }
                for (; j < j1; ++j) {
                    float s = cand_s(hx, hy, hz, g_slp4[j]);
                    if (s < q[KSEL - 1]) insert32(q, s);
                }
            }
        }
    }

    // ---- Pass 2: fixed threshold T, same fmaf chain (bit-identical), collect ----
    const float T = q[KSEL - 1];
    const float thrF = T + h2;
    int cnt = 0;
    float wsum = 0.0f;
    const int ob = p * KSEL;
    {
        float wz = sqrtf(fmaxf(thrF, 0.0f));
        int z0 = cellof(hz - wz), z1 = cellof(hz + wz);
        for (int gz = z0; gz <= z1; ++gz) {
            float mz = mindc(hz, gz);
            float remz = thrF - mz * mz;
            if (remz < 0.0f) continue;
            float wy = sqrtf(remz);
            int y0 = cellof(hy - wy), y1 = cellof(hy + wy);
            for (int gy = y0; gy <= y1; ++gy) {
                float my = mindc(hy, gy);
                float rem = remz - my * my;
                if (rem < 0.0f) continue;
                float halfw = sqrtf(rem);
                int gx0 = cellof(hx - halfw);
                int gx1 = cellof(hx + halfw);
                int rowb = (gz << 10) | (gy << 5);
                int sc0 = g_scell[rowb | gx0];
                int sc1 = g_scell[rowb | gx1];
                int j  = sc0 & 0xffff;
                int j1 = (sc1 & 0xffff) + (sc1 >> 16);
                for (; j < j1; ++j) {
                    float s = cand_s(hx, hy, hz, g_slp4[j]);
                    if (s <= T && cnt < KSEL) {
                        float wg = 1.0f / fmaxf(s + h2, 1e-16f);
                        g_tki[ob + cnt] = j;
                        g_tkw[ob + cnt] = wg;
                        wsum += wg;
                        cnt++;
                    }
                }
            }
        }
    }
    while (cnt < KSEL) { g_tki[ob + cnt] = 0; g_tkw[ob + cnt] = 0.0f; cnt++; }
    g_twsum[p] = wsum;
}

// ---------------- gather kernel: one warp per target ----------------
__global__ __launch_bounds__(256) void gather_kernel(float* __restrict__ out) {
    const int lane = threadIdx.x & 31;
    const int p = blockIdx.x * 8 + (threadIdx.x >> 5);

    int   myid = g_tki[p * KSEL + lane];
    float myw  = g_tkw[p * KSEL + lane];

    float4 acc = make_float4(0.f, 0.f, 0.f, 0.f);
#pragma unroll
    for (int k = 0; k < KSEL; k++) {
        int   id = __shfl_sync(FULLM, myid, k);
        float wk = __shfl_sync(FULLM, myw, k);
        float4 v = g_xs4[id * (FDIM/4) + lane];
        acc.x = fmaf(wk, v.x, acc.x);
        acc.y = fmaf(wk, v.y, acc.y);
        acc.z = fmaf(wk, v.z, acc.z);
        acc.w = fmaf(wk, v.w, acc.w);
    }
    float inv = 1.0f / g_twsum[p];
    int o = g_order[p];
    float4* out4 = (float4*)out;
    out4[o * (FDIM/4) + lane] =
        make_float4(acc.x * inv, acc.y * inv, acc.z * inv, acc.w * inv);
}

extern "C" void kernel_launch(void* const* d_in, const int* in_sizes, int n_in,
                              void* d_out, int out_size) {
    const float* x     = (const float*)d_in[0];
    const float* pos_l = (const float*)d_in[1];
    const float* pos_h = (const float*)d_in[2];
    float* out = (float*)d_out;

    zero_kernel<<<NBINS / 256, 256>>>();
    bin_t_kernel<<<N_H / 256, 256>>>(pos_h);
    bin_s_kernel<<<N_L / 256, 256>>>(pos_l);
    prefix32k_kernel<<<1, 1024>>>(0);
    prefix32k_kernel<<<1, 1024>>>(1);
    pack_scell_kernel<<<NBINS / 256, 256>>>();
    scatter_t_kernel<<<N_H / 256, 256>>>(pos_h);
    scatter_s_kernel<<<N_L / 256, 256>>>(pos_l);
    xcopy_kernel<<<N_L / 8, 256>>>(x);
    select_kernel<<<N_H / 128, 128>>>();
    gather_kernel<<<N_H / 8, 256>>>(out);
}

// round 14
// speedup vs baseline: 22.9451x; 1.1058x over previous
#include <cuda_runtime.h>

#define N_L    8192
#define N_H    32768
#define FDIM   128
#define KSEL   32

#define GRID   32
#define NBINS  (GRID * GRID * GRID)
#define GLO    (-6.0f)
#define CS     0.375f
#define HALF   (0.5f * CS)
#define CSINV  2.6666667f
#define FULLM  0xffffffffu
#define LOGCAP 192

// ---------------- static device scratch (allocation-free) ----------------
__device__ float4 g_slp4[N_L];            // sorted sources (x,y,z,|l|^2)
__device__ float4 g_th4[N_H];             // sorted targets (x,y,z,|h|^2)
__device__ float4 g_xs4[N_L * (FDIM/4)];  // x rows permuted to sorted source order
__device__ int    g_thist[NBINS], g_tcur[NBINS], g_tstart[NBINS];
__device__ int    g_shist[NBINS], g_scur[NBINS], g_sstart[NBINS];
__device__ int    g_scell[NBINS];         // start | (count<<16)
__device__ int    g_tbin[N_H], g_sbin[N_L], g_spos[N_L], g_order[N_H];
__device__ float2 g_log[N_H * LOGCAP];    // per-target insert-event log (s, idx-bits)
__device__ int    g_tki[N_H * KSEL];
__device__ float  g_tkw[N_H * KSEL];
__device__ float  g_twsum[N_H];

// ---------------- prep kernels ----------------
__global__ void zero_kernel() {
    int i = blockIdx.x * blockDim.x + threadIdx.x;
    if (i < NBINS) { g_thist[i] = 0; g_shist[i] = 0; }
}

__device__ __forceinline__ int cellc(float v) {
    int c = (int)((v - GLO) * CSINV);
    return min(max(c, 0), GRID - 1);
}
__device__ __forceinline__ int cellof(float v) {
    int c = (int)floorf((v - GLO) * CSINV);
    return min(max(c, 0), GRID - 1);
}

__device__ __forceinline__ int spread5(int b) {
    return (b & 1) | ((b & 2) << 2) | ((b & 4) << 4) | ((b & 8) << 6) | ((b & 16) << 8);
}

__global__ void bin_t_kernel(const float* __restrict__ pos_h) {
    int i = blockIdx.x * blockDim.x + threadIdx.x;
    if (i < N_H) {
        int cx = cellc(pos_h[3*i+0]);
        int cy = cellc(pos_h[3*i+1]);
        int cz = cellc(pos_h[3*i+2]);
        int m = spread5(cx) | (spread5(cy) << 1) | (spread5(cz) << 2);  // Morton
        g_tbin[i] = m;
        atomicAdd(&g_thist[m], 1);
    }
}

__global__ void bin_s_kernel(const float* __restrict__ pos_l) {
    int i = blockIdx.x * blockDim.x + threadIdx.x;
    if (i < N_L) {
        int cx = cellc(pos_l[3*i+0]);
        int cy = cellc(pos_l[3*i+1]);
        int cz = cellc(pos_l[3*i+2]);
        int b = (cz << 10) | (cy << 5) | cx;                            // linear
        g_sbin[i] = b;
        atomicAdd(&g_shist[b], 1);
    }
}

// Exclusive prefix over 32768 bins, int4-vectorized. block 0: targets, block 1: sources.
__global__ void prefix32k_kernel() {
    int sel = blockIdx.x;
    const int* __restrict__ hist = sel ? g_shist : g_thist;
    int* cursor   = sel ? g_scur   : g_tcur;
    int* startarr = sel ? g_sstart : g_tstart;

    __shared__ int s_part[1024];
    int t = threadIdx.x;
    int base = t * 32;
    const int4* h4 = (const int4*)(hist + base);
    int4 v[8];
    int sum = 0;
#pragma unroll
    for (int j = 0; j < 8; j++) {
        v[j] = h4[j];
        sum += v[j].x + v[j].y + v[j].z + v[j].w;
    }
    s_part[t] = sum;
    __syncthreads();
    for (int d = 1; d < 1024; d <<= 1) {
        int add = (t >= d) ? s_part[t - d] : 0;
        __syncthreads();
        s_part[t] += add;
        __syncthreads();
    }
    int run = t ? s_part[t - 1] : 0;
#pragma unroll
    for (int j = 0; j < 8; j++) {
        int4 c;
        c.x = run; run += v[j].x;
        c.y = run; run += v[j].y;
        c.z = run; run += v[j].z;
        c.w = run; run += v[j].w;
        ((int4*)(cursor   + base))[j] = c;
        ((int4*)(startarr + base))[j] = c;
    }
}

__global__ void pack_scell_kernel() {
    int i = blockIdx.x * blockDim.x + threadIdx.x;
    if (i < NBINS) g_scell[i] = g_sstart[i] | (g_shist[i] << 16);
}

__global__ void scatter_t_kernel(const float* __restrict__ pos_h) {
    int i = blockIdx.x * blockDim.x + threadIdx.x;
    if (i < N_H) {
        float x = pos_h[3*i+0], y = pos_h[3*i+1], z = pos_h[3*i+2];
        int p = atomicAdd(&g_tcur[g_tbin[i]], 1);
        g_order[p] = i;
        g_th4[p] = make_float4(x, y, z, fmaf(x, x, fmaf(y, y, z * z)));
    }
}

__global__ void scatter_s_kernel(const float* __restrict__ pos_l) {
    int i = blockIdx.x * blockDim.x + threadIdx.x;
    if (i < N_L) {
        float x = pos_l[3*i+0], y = pos_l[3*i+1], z = pos_l[3*i+2];
        int p = atomicAdd(&g_scur[g_sbin[i]], 1);
        g_spos[i] = p;
        g_slp4[p] = make_float4(x, y, z, fmaf(x, x, fmaf(y, y, z * z)));
    }
}

__global__ void xcopy_kernel(const float* __restrict__ x) {
    int i = blockIdx.x * 8 + (threadIdx.x >> 5);
    int c = threadIdx.x & 31;
    const float4* __restrict__ x4 = (const float4*)x;
    g_xs4[g_spos[i] * (FDIM/4) + c] = x4[i * (FDIM/4) + c];
}

// ---------------- select kernel ----------------
__device__ __forceinline__ float cand_s(float hx, float hy, float hz, float4 p) {
    float dot = fmaf(hx, p.x, fmaf(hy, p.y, hz * p.z));
    return fmaf(-2.0f, dot, p.w);
}

__device__ __forceinline__ void insert32(float (&q)[KSEL], float s) {
    float cur = s;
#pragma unroll
    for (int j = 0; j < KSEL; j++) {
        float lo = fminf(q[j], cur);
        cur = fmaxf(q[j], cur);
        q[j] = lo;
    }
}

__device__ __forceinline__ float mindc(float h, int g) {
    return fmaxf(fabsf(h - (GLO + (g + 0.5f) * CS)) - HALF, 0.0f);
}

// Insert + append (s, j) to the per-target event log (EXACT s value — any point
// with final s <= T was never evicted after its insert event, so the log
// contains every winner; filtering by s <= T recovers them exactly).
#define INS_LOG(SV, JV)                                                \
    do {                                                               \
        insert32(q, (SV));                                             \
        if (logcnt < LOGCAP) g_log[lb + logcnt] =                      \
            make_float2((SV), __int_as_float(JV));                     \
        logcnt++;                                                      \
    } while (0)

__global__ __launch_bounds__(128) void select_kernel() {
    const int p = blockIdx.x * blockDim.x + threadIdx.x;   // one thread = one target

    const float4 th = g_th4[p];
    const float hx = th.x, hy = th.y, hz = th.z, h2 = th.w;

    const int cx = cellc(hx), cy = cellc(hy), cz = cellc(hz);
    const float e = fmaxf(fabsf(hx - (GLO + (cx + 0.5f) * CS)),
                    fmaxf(fabsf(hy - (GLO + (cy + 0.5f) * CS)),
                          fabsf(hz - (GLO + (cz + 0.5f) * CS))));

    // ---- Count-prepass: smallest cube (Chebyshev radius cc) holding >= 32 sources ----
    int cc = 0;
    for (; cc < GRID; ++cc) {
        int zlo = max(cz - cc, 0), zhi = min(cz + cc, GRID - 1);
        int ylo = max(cy - cc, 0), yhi = min(cy + cc, GRID - 1);
        int xlo = max(cx - cc, 0), xhi = min(cx + cc, GRID - 1);
        int total = 0;
        for (int gz = zlo; gz <= zhi; ++gz)
            for (int gy = ylo; gy <= yhi; ++gy) {
                int rowb = (gz << 10) | (gy << 5);
                int sc0 = g_scell[rowb | xlo];
                int sc1 = g_scell[rowb | xhi];
                total += (sc1 & 0xffff) + (sc1 >> 16) - (sc0 & 0xffff);
            }
        if (total >= KSEL) break;
    }
    const float reach = (cc + 0.5f) * CS + e;
    const float thr0 = 3.0f * reach * reach;   // valid upper bound on 32nd d2

    float q[KSEL];
#pragma unroll
    for (int j = 0; j < KSEL; j++) q[j] = __int_as_float(0x7f800000);

    int logcnt = 0;
    const int lb = p * LOGCAP;

    // ---- Pass 1: rows near-to-far, analytic x-span, exact value bubble + log ----
    {
        int zdone = 0;
        for (int iz = 0; iz < 2 * GRID && zdone != 3; ++iz) {
            int dz = (iz & 1) ? ((iz >> 1) + 1) : -(iz >> 1);
            if (iz && ((dz < 0 && (zdone & 1)) || (dz > 0 && (zdone & 2)))) continue;
            int gz = cz + dz;
            if ((unsigned)gz >= GRID) { zdone |= (dz < 0) ? 1 : 2; continue; }
            float mz = mindc(hz, gz);
            float mz2 = mz * mz;
            float thr = fminf(thr0, q[KSEL - 1] + h2);
            if (mz2 > thr) { if (dz) zdone |= (dz < 0) ? 1 : 2; continue; }

            int ydone = 0;
            for (int iy = 0; iy < 2 * GRID && ydone != 3; ++iy) {
                int dy = (iy & 1) ? ((iy >> 1) + 1) : -(iy >> 1);
                if (iy && ((dy < 0 && (ydone & 1)) || (dy > 0 && (ydone & 2)))) continue;
                int gy = cy + dy;
                if ((unsigned)gy >= GRID) { ydone |= (dy < 0) ? 1 : 2; continue; }
                float my = mindc(hy, gy);
                thr = fminf(thr0, q[KSEL - 1] + h2);
                float rem = thr - mz2 - my * my;
                if (rem < 0.0f) { if (dy) ydone |= (dy < 0) ? 1 : 2; continue; }

                float halfw = sqrtf(rem);
                int gx0 = cellof(hx - halfw);
                int gx1 = cellof(hx + halfw);
                int rowb = (gz << 10) | (gy << 5);
                int sc0 = g_scell[rowb | gx0];
                int sc1 = g_scell[rowb | gx1];
                int j  = sc0 & 0xffff;
                int j1 = (sc1 & 0xffff) + (sc1 >> 16);

                for (; j + 4 <= j1; j += 4) {
                    float4 p0 = g_slp4[j + 0];
                    float4 p1 = g_slp4[j + 1];
                    float4 p2 = g_slp4[j + 2];
                    float4 p3 = g_slp4[j + 3];
                    float s0 = cand_s(hx, hy, hz, p0);
                    float s1 = cand_s(hx, hy, hz, p1);
                    float s2 = cand_s(hx, hy, hz, p2);
                    float s3 = cand_s(hx, hy, hz, p3);
                    float m = fminf(fminf(s0, s1), fminf(s2, s3));
                    if (m < q[KSEL - 1]) {
                        if (s0 < q[KSEL - 1]) INS_LOG(s0, j + 0);
                        if (s1 < q[KSEL - 1]) INS_LOG(s1, j + 1);
                        if (s2 < q[KSEL - 1]) INS_LOG(s2, j + 2);
                        if (s3 < q[KSEL - 1]) INS_LOG(s3, j + 3);
                    }
                }
                for (; j < j1; ++j) {
                    float s = cand_s(hx, hy, hz, g_slp4[j]);
                    if (s < q[KSEL - 1]) INS_LOG(s, j);
                }
            }
        }
    }

    const float T = q[KSEL - 1];
    int cnt = 0;
    float wsum = 0.0f;
    const int ob = p * KSEL;

    if (logcnt <= LOGCAP) {
        // ---- Recover winners from the event log (exact compare on stored s) ----
#pragma unroll 1
        for (int i = 0; i < logcnt; ++i) {
            float2 en = g_log[lb + i];
            if (en.x <= T && cnt < KSEL) {
                float wg = 1.0f / fmaxf(en.x + h2, 1e-16f);
                g_tki[ob + cnt] = __float_as_int(en.y);
                g_tkw[ob + cnt] = wg;
                wsum += wg;
                cnt++;
            }
        }
    } else {
        // ---- Rare overflow fallback: exact row-walk rescan (same fmaf chain) ----
        const float thrF = T + h2;
        float wz = sqrtf(fmaxf(thrF, 0.0f));
        int z0 = cellof(hz - wz), z1 = cellof(hz + wz);
        for (int gz = z0; gz <= z1; ++gz) {
            float mz = mindc(hz, gz);
            float remz = thrF - mz * mz;
            if (remz < 0.0f) continue;
            float wy = sqrtf(remz);
            int y0 = cellof(hy - wy), y1 = cellof(hy + wy);
            for (int gy = y0; gy <= y1; ++gy) {
                float my = mindc(hy, gy);
                float rem = remz - my * my;
                if (rem < 0.0f) continue;
                float halfw = sqrtf(rem);
                int gx0 = cellof(hx - halfw);
                int gx1 = cellof(hx + halfw);
                int rowb = (gz << 10) | (gy << 5);
                int sc0 = g_scell[rowb | gx0];
                int sc1 = g_scell[rowb | gx1];
                int j  = sc0 & 0xffff;
                int j1 = (sc1 & 0xffff) + (sc1 >> 16);
                for (; j < j1; ++j) {
                    float s = cand_s(hx, hy, hz, g_slp4[j]);
                    if (s <= T && cnt < KSEL) {
                        float wg = 1.0f / fmaxf(s + h2, 1e-16f);
                        g_tki[ob + cnt] = j;
                        g_tkw[ob + cnt] = wg;
                        wsum += wg;
                        cnt++;
                    }
                }
            }
        }
    }
    while (cnt < KSEL) { g_tki[ob + cnt] = 0; g_tkw[ob + cnt] = 0.0f; cnt++; }
    g_twsum[p] = wsum;
}

// ---------------- gather kernel: one warp per target ----------------
__global__ __launch_bounds__(256) void gather_kernel(float* __restrict__ out) {
    const int lane = threadIdx.x & 31;
    const int p = blockIdx.x * 8 + (threadIdx.x >> 5);

    int   myid = g_tki[p * KSEL + lane];
    float myw  = g_tkw[p * KSEL + lane];

    float4 acc = make_float4(0.f, 0.f, 0.f, 0.f);
#pragma unroll
    for (int k = 0; k < KSEL; k++) {
        int   id = __shfl_sync(FULLM, myid, k);
        float wk = __shfl_sync(FULLM, myw, k);
        float4 v = g_xs4[id * (FDIM/4) + lane];
        acc.x = fmaf(wk, v.x, acc.x);
        acc.y = fmaf(wk, v.y, acc.y);
        acc.z = fmaf(wk, v.z, acc.z);
        acc.w = fmaf(wk, v.w, acc.w);
    }
    float inv = 1.0f / g_twsum[p];
    int o = g_order[p];
    float4* out4 = (float4*)out;
    out4[o * (FDIM/4) + lane] =
        make_float4(acc.x * inv, acc.y * inv, acc.z * inv, acc.w * inv);
}

extern "C" void kernel_launch(void* const* d_in, const int* in_sizes, int n_in,
                              void* d_out, int out_size) {
    const float* x     = (const float*)d_in[0];
    const float* pos_l = (const float*)d_in[1];
    const float* pos_h = (const float*)d_in[2];
    float* out = (float*)d_out;

    zero_kernel<<<NBINS / 256, 256>>>();
    bin_t_kernel<<<N_H / 256, 256>>>(pos_h);
    bin_s_kernel<<<N_L / 256, 256>>>(pos_l);
    prefix32k_kernel<<<2, 1024>>>();
    pack_scell_kernel<<<NBINS / 256, 256>>>();
    scatter_t_kernel<<<N_H / 256, 256>>>(pos_h);
    scatter_s_kernel<<<N_L / 256, 256>>>(pos_l);
    xcopy_kernel<<<N_L / 8, 256>>>(x);
    select_kernel<<<N_H / 128, 128>>>();
    gather_kernel<<<N_H / 8, 256>>>(out);
}